// round 1
// baseline (speedup 1.0000x reference)
#include <cuda_runtime.h>

#define BATCH   2
#define SEQ     2048
#define DMODEL  1024
#define NHEADS  16
#define HDIM    64
#define MROWS   (BATCH*SEQ)   // 4096

// -------- scratch (device globals; no allocation allowed) --------
__device__ float g_q[BATCH*NHEADS*SEQ*HDIM];   // [b][h][s][d]
__device__ float g_k[BATCH*NHEADS*SEQ*HDIM];
__device__ float g_v[BATCH*NHEADS*SEQ*HDIM];
__device__ float g_att[MROWS*DMODEL];          // merged [b][s][h*64+d]

// ================= GEMM: out = X[M,K] @ W[K,N] + bias =================
// M=4096, N=K=1024.  BM=128, BN=128, BK=8, 256 threads, 8x8 per thread.
#define BM 128
#define BN 128
#define BK 8

template<bool HEADOUT>
__global__ __launch_bounds__(256, 2)
void gemm_bias_kernel(const float* __restrict__ X,
                      const float* __restrict__ W,
                      const float* __restrict__ bias,
                      float* __restrict__ out)
{
    __shared__ float As[BK][BM];
    __shared__ float Bs[BK][BN];

    const int tid = threadIdx.x;
    const int bx = blockIdx.x;   // N/BN = 8
    const int by = blockIdx.y;   // M/BM = 32
    const int tx = tid & 15;     // 0..15
    const int ty = tid >> 4;     // 0..15

    float acc[8][8];
    #pragma unroll
    for (int i = 0; i < 8; i++)
        #pragma unroll
        for (int j = 0; j < 8; j++) acc[i][j] = 0.f;

    const int arow  = tid >> 1;          // 0..127
    const int ak4   = (tid & 1) * 4;     // 0 or 4
    const int brow  = tid >> 5;          // 0..7
    const int bcol4 = (tid & 31) * 4;    // 0..124

    const float* Xp = X + (size_t)(by * BM + arow) * DMODEL;
    const float* Wp = W + bx * BN;

    for (int k0 = 0; k0 < DMODEL; k0 += BK) {
        float4 av = *(const float4*)(Xp + k0 + ak4);
        As[ak4 + 0][arow] = av.x;
        As[ak4 + 1][arow] = av.y;
        As[ak4 + 2][arow] = av.z;
        As[ak4 + 3][arow] = av.w;
        float4 bv = *(const float4*)(Wp + (size_t)(k0 + brow) * DMODEL + bcol4);
        *(float4*)&Bs[brow][bcol4] = bv;
        __syncthreads();

        #pragma unroll
        for (int kk = 0; kk < BK; kk++) {
            float a[8], b[8];
            #pragma unroll
            for (int i = 0; i < 8; i++) a[i] = As[kk][ty * 8 + i];
            #pragma unroll
            for (int j = 0; j < 8; j++) b[j] = Bs[kk][tx * 8 + j];
            #pragma unroll
            for (int i = 0; i < 8; i++)
                #pragma unroll
                for (int j = 0; j < 8; j++) acc[i][j] += a[i] * b[j];
        }
        __syncthreads();
    }

    const int r0 = by * BM + ty * 8;
    const int c0 = bx * BN + tx * 8;
    #pragma unroll
    for (int i = 0; i < 8; i++) {
        const int R = r0 + i;
        #pragma unroll
        for (int j = 0; j < 8; j++) {
            const int c = c0 + j;
            float v = acc[i][j] + bias[c];
            if (HEADOUT) {
                const int b = R / SEQ, s = R % SEQ;
                const int h = c / HDIM, d = c % HDIM;
                out[(((size_t)(b * NHEADS + h) * SEQ) + s) * HDIM + d] = v;
            } else {
                out[(size_t)R * DMODEL + c] = v;
            }
        }
    }
}

// ================= Flash attention (fp32, online softmax) =================
// One block = one (b, h, 64-query tile). 256 threads.
// Thread t: row r = t/4 (0..63), column group cgrp = t%4.
// Scores: thread owns columns c = cgrp + 4*cc, cc=0..15 (interleaved -> conflict-free LDS).
// PV:     thread owns dims  d = cgrp*16 .. +16.
#define TQ 64
#define TKT 64
#define SP 68   // smem row stride (floats); keeps float4 alignment

__global__ __launch_bounds__(256, 2)
void attn_kernel(const float* __restrict__ Q,
                 const float* __restrict__ K,
                 const float* __restrict__ V,
                 float* __restrict__ out)
{
    extern __shared__ float sm[];
    float* Qs  = sm;                 // TQ x SP
    float* KVs = sm + TQ * SP;       // TKT x SP (K tile, then V tile)
    float* Ps  = sm + 2 * TQ * SP;   // TQ x SP

    const int tid  = threadIdx.x;
    const int qt   = blockIdx.x;   // 0..31
    const int h    = blockIdx.y;
    const int b    = blockIdx.z;
    const int r    = tid >> 2;     // 0..63
    const int cgrp = tid & 3;      // 0..3

    const size_t headbase = ((size_t)(b * NHEADS + h)) * SEQ * HDIM;
    const float* Qg = Q + headbase + (size_t)qt * TQ * HDIM;

    // load Q tile (64x64) -> Qs
    #pragma unroll
    for (int i = 0; i < 4; i++) {
        const int lin = tid + i * 256;       // float4 index, 1024 total
        const int row = lin >> 4, c4 = (lin & 15) * 4;
        float4 v4 = *(const float4*)(Qg + row * HDIM + c4);
        *(float4*)&Qs[row * SP + c4] = v4;
    }

    float m = -1e30f, l = 0.f;
    float oacc[16];
    #pragma unroll
    for (int j = 0; j < 16; j++) oacc[j] = 0.f;

    const int d0 = cgrp * 16;

    for (int kt = 0; kt < SEQ / TKT; kt++) {
        __syncthreads();   // prior PV reads of KVs / Ps done
        // load K tile -> KVs
        const float* Kg = K + headbase + (size_t)kt * TKT * HDIM;
        #pragma unroll
        for (int i = 0; i < 4; i++) {
            const int lin = tid + i * 256;
            const int row = lin >> 4, c4 = (lin & 15) * 4;
            *(float4*)&KVs[row * SP + c4] = *(const float4*)(Kg + row * HDIM + c4);
        }
        __syncthreads();

        // scores: p[cc] = 0.125 * dot(Q[r], K[cgrp+4cc])
        float p[16];
        #pragma unroll
        for (int cc = 0; cc < 16; cc++) p[cc] = 0.f;
        for (int k4 = 0; k4 < HDIM; k4 += 4) {
            float4 qv = *(const float4*)&Qs[r * SP + k4];
            #pragma unroll
            for (int cc = 0; cc < 16; cc++) {
                const int c = cgrp + cc * 4;
                float4 kv = *(const float4*)&KVs[c * SP + k4];
                p[cc] += qv.x * kv.x + qv.y * kv.y + qv.z * kv.z + qv.w * kv.w;
            }
        }
        float mloc = -1e30f;
        #pragma unroll
        for (int cc = 0; cc < 16; cc++) {
            p[cc] *= 0.125f;
            mloc = fmaxf(mloc, p[cc]);
        }
        mloc = fmaxf(mloc, __shfl_xor_sync(0xffffffffu, mloc, 1));
        mloc = fmaxf(mloc, __shfl_xor_sync(0xffffffffu, mloc, 2));
        const float mnew = fmaxf(m, mloc);

        float lloc = 0.f;
        #pragma unroll
        for (int cc = 0; cc < 16; cc++) {
            p[cc] = __expf(p[cc] - mnew);
            lloc += p[cc];
        }
        lloc += __shfl_xor_sync(0xffffffffu, lloc, 1);
        lloc += __shfl_xor_sync(0xffffffffu, lloc, 2);

        const float alpha = __expf(m - mnew);
        l = l * alpha + lloc;
        m = mnew;
        #pragma unroll
        for (int j = 0; j < 16; j++) oacc[j] *= alpha;

        #pragma unroll
        for (int cc = 0; cc < 16; cc++) Ps[r * SP + cgrp + cc * 4] = p[cc];
        __syncthreads();   // Ps ready; KVs free

        // load V tile -> KVs
        const float* Vg = V + headbase + (size_t)kt * TKT * HDIM;
        #pragma unroll
        for (int i = 0; i < 4; i++) {
            const int lin = tid + i * 256;
            const int row = lin >> 4, c4 = (lin & 15) * 4;
            *(float4*)&KVs[row * SP + c4] = *(const float4*)(Vg + row * HDIM + c4);
        }
        __syncthreads();

        // O[r, d0..d0+16) += P[r, :] @ V[:, d0..d0+16)
        for (int c = 0; c < TKT; c++) {
            const float pv = Ps[r * SP + c];
            const float* Vr = &KVs[c * SP + d0];
            #pragma unroll
            for (int jj = 0; jj < 4; jj++) {
                float4 v4 = *(const float4*)(Vr + jj * 4);
                oacc[jj * 4 + 0] += pv * v4.x;
                oacc[jj * 4 + 1] += pv * v4.y;
                oacc[jj * 4 + 2] += pv * v4.z;
                oacc[jj * 4 + 3] += pv * v4.w;
            }
        }
    }

    const float inv = 1.f / l;
    const int srow = qt * TQ + r;
    float* og = out + ((size_t)b * SEQ + srow) * DMODEL + h * HDIM + d0;
    #pragma unroll
    for (int j = 0; j < 16; j++) og[j] = oacc[j] * inv;
}

// ============================== launch ==============================
extern "C" void kernel_launch(void* const* d_in, const int* in_sizes, int n_in,
                              void* d_out, int out_size)
{
    const float* X  = (const float*)d_in[0];
    const float* Wq = (const float*)d_in[1];
    const float* bq = (const float*)d_in[2];
    const float* Wk = (const float*)d_in[3];
    const float* bk = (const float*)d_in[4];
    const float* Wv = (const float*)d_in[5];
    const float* bv = (const float*)d_in[6];
    const float* Wo = (const float*)d_in[7];
    const float* bo = (const float*)d_in[8];

    float *qp, *kp, *vp, *ap;
    cudaGetSymbolAddress((void**)&qp, g_q);
    cudaGetSymbolAddress((void**)&kp, g_k);
    cudaGetSymbolAddress((void**)&vp, g_v);
    cudaGetSymbolAddress((void**)&ap, g_att);

    dim3 ggrid(DMODEL / BN, MROWS / BM);   // (8, 32)
    gemm_bias_kernel<true><<<ggrid, 256>>>(X, Wq, bq, qp);
    gemm_bias_kernel<true><<<ggrid, 256>>>(X, Wk, bk, kp);
    gemm_bias_kernel<true><<<ggrid, 256>>>(X, Wv, bv, vp);

    const size_t smem = (size_t)3 * TQ * SP * sizeof(float);   // 52224 B
    cudaFuncSetAttribute(attn_kernel, cudaFuncAttributeMaxDynamicSharedMemorySize, (int)smem);
    attn_kernel<<<dim3(SEQ / TQ, NHEADS, BATCH), 256, smem>>>(qp, kp, vp, ap);

    gemm_bias_kernel<false><<<ggrid, 256>>>(ap, Wo, bo, (float*)d_out);
}

// round 2
// speedup vs baseline: 6.0594x; 6.0594x over previous
#include <cuda_runtime.h>
#include <cstdint>

#define BATCH   2
#define SEQ     2048
#define DMODEL  1024
#define NHEADS  16
#define HDIM    64
#define MROWS   (BATCH*SEQ)   // 4096

// -------- scratch (device globals; no allocation allowed) --------
__device__ float g_q[BATCH*NHEADS*SEQ*HDIM];   // [b][h][s][d]
__device__ float g_k[BATCH*NHEADS*SEQ*HDIM];
__device__ float g_v[BATCH*NHEADS*SEQ*HDIM];
__device__ float g_att[MROWS*DMODEL];          // merged [b][s][h*64+d]

// ---------------- tf32 helpers ----------------
__device__ __forceinline__ uint32_t f2t(float x) {
    uint32_t r;
    asm("cvt.rna.tf32.f32 %0, %1;" : "=r"(r) : "f"(x));
    return r;
}

// D += A * B   (m16n8k8, A row-major, B col-major, fp32 accum)
__device__ __forceinline__ void mma_tf32(float* d, const uint32_t* a, const uint32_t* b) {
    asm volatile(
        "mma.sync.aligned.m16n8k8.row.col.f32.tf32.tf32.f32 "
        "{%0,%1,%2,%3}, {%4,%5,%6,%7}, {%8,%9}, {%0,%1,%2,%3};\n"
        : "+f"(d[0]), "+f"(d[1]), "+f"(d[2]), "+f"(d[3])
        : "r"(a[0]), "r"(a[1]), "r"(a[2]), "r"(a[3]),
          "r"(b[0]), "r"(b[1]));
}

// ================= GEMM (tf32 tensor core): out = X[M,K] @ W[K,N] + bias ==========
// M=4096, N=K=1024. Block 128x128, BK=16, 256 threads = 8 warps (2x4), warp 64x32.
#define ASTRIDE 20     // As[m][k] row stride (words): bank = (20g + t4) distinct
#define BSTRIDE 136    // Bs[k][n] row stride (words): bank = (8t4 + g) distinct

template<bool HEADOUT>
__global__ __launch_bounds__(256, 2)
void gemm_tf32(const float* __restrict__ X,
               const float* __restrict__ W,
               const float* __restrict__ bias,
               float* __restrict__ out)
{
    __shared__ uint32_t As[128 * ASTRIDE];   // [m][k] 10240 B
    __shared__ uint32_t Bs[16 * BSTRIDE];    // [k][n]  8704 B

    const int tid  = threadIdx.x;
    const int bx   = blockIdx.x;   // N/128 = 8
    const int by   = blockIdx.y;   // M/128 = 32
    const int wid  = tid >> 5;
    const int lane = tid & 31;
    const int g    = lane >> 2;    // 0..7
    const int t4   = lane & 3;     // 0..3
    const int m0   = (wid & 1) * 64;
    const int n0   = (wid >> 1) * 32;

    const int am = tid >> 1;            // 0..127
    const int ak = (tid & 1) * 8;       // 0 or 8
    const int bk = tid >> 4;            // 0..15
    const int bn = (tid & 15) * 4;      // 0..60

    const float* Xp = X + (size_t)(by * 128 + am) * DMODEL;
    const float* Wp = W + bx * 128;

    float acc[4][4][4];
    #pragma unroll
    for (int i = 0; i < 4; i++)
        #pragma unroll
        for (int j = 0; j < 4; j++)
            #pragma unroll
            for (int r = 0; r < 4; r++) acc[i][j][r] = 0.f;

    // prologue prefetch (k0 = 0)
    float4 pa0 = *(const float4*)(Xp + ak);
    float4 pa1 = *(const float4*)(Xp + ak + 4);
    float4 pb0 = *(const float4*)(Wp + (size_t)bk * DMODEL + bn);
    float4 pb1 = *(const float4*)(Wp + (size_t)bk * DMODEL + bn + 64);

    for (int k0 = 0; k0 < DMODEL; k0 += 16) {
        {
            uint4 u0 = {f2t(pa0.x), f2t(pa0.y), f2t(pa0.z), f2t(pa0.w)};
            uint4 u1 = {f2t(pa1.x), f2t(pa1.y), f2t(pa1.z), f2t(pa1.w)};
            *(uint4*)&As[am * ASTRIDE + ak]     = u0;
            *(uint4*)&As[am * ASTRIDE + ak + 4] = u1;
            uint4 v0 = {f2t(pb0.x), f2t(pb0.y), f2t(pb0.z), f2t(pb0.w)};
            uint4 v1 = {f2t(pb1.x), f2t(pb1.y), f2t(pb1.z), f2t(pb1.w)};
            *(uint4*)&Bs[bk * BSTRIDE + bn]      = v0;
            *(uint4*)&Bs[bk * BSTRIDE + bn + 64] = v1;
        }
        __syncthreads();

        if (k0 + 16 < DMODEL) {
            pa0 = *(const float4*)(Xp + k0 + 16 + ak);
            pa1 = *(const float4*)(Xp + k0 + 16 + ak + 4);
            pb0 = *(const float4*)(Wp + (size_t)(k0 + 16 + bk) * DMODEL + bn);
            pb1 = *(const float4*)(Wp + (size_t)(k0 + 16 + bk) * DMODEL + bn + 64);
        }

        #pragma unroll
        for (int kk = 0; kk < 16; kk += 8) {
            uint32_t af[4][4], bf[4][2];
            #pragma unroll
            for (int j = 0; j < 4; j++) {
                bf[j][0] = Bs[(kk + t4) * BSTRIDE + n0 + j * 8 + g];
                bf[j][1] = Bs[(kk + t4 + 4) * BSTRIDE + n0 + j * 8 + g];
            }
            #pragma unroll
            for (int i = 0; i < 4; i++) {
                const int ra = m0 + i * 16 + g;
                af[i][0] = As[ra * ASTRIDE + kk + t4];
                af[i][1] = As[(ra + 8) * ASTRIDE + kk + t4];
                af[i][2] = As[ra * ASTRIDE + kk + t4 + 4];
                af[i][3] = As[(ra + 8) * ASTRIDE + kk + t4 + 4];
            }
            #pragma unroll
            for (int i = 0; i < 4; i++)
                #pragma unroll
                for (int j = 0; j < 4; j++)
                    mma_tf32(acc[i][j], af[i], bf[j]);
        }
        __syncthreads();
    }

    // epilogue
    #pragma unroll
    for (int i = 0; i < 4; i++) {
        const int Ra = by * 128 + m0 + i * 16 + g;
        #pragma unroll
        for (int j = 0; j < 4; j++) {
            const int c = bx * 128 + n0 + j * 8 + 2 * t4;
            const float b0v = bias[c], b1v = bias[c + 1];
            float2 v0 = {acc[i][j][0] + b0v, acc[i][j][1] + b1v};
            float2 v1 = {acc[i][j][2] + b0v, acc[i][j][3] + b1v};
            if (HEADOUT) {
                const int h = c >> 6, d = c & 63;
                {
                    const int bb = Ra >> 11, s = Ra & 2047;
                    *(float2*)&out[(((size_t)(bb * NHEADS + h) * SEQ) + s) * HDIM + d] = v0;
                }
                {
                    const int R2 = Ra + 8;
                    const int bb = R2 >> 11, s = R2 & 2047;
                    *(float2*)&out[(((size_t)(bb * NHEADS + h) * SEQ) + s) * HDIM + d] = v1;
                }
            } else {
                *(float2*)&out[(size_t)Ra * DMODEL + c] = v0;
                *(float2*)&out[(size_t)(Ra + 8) * DMODEL + c] = v1;
            }
        }
    }
}

// ========== Flash attention, tf32 tensor cores ==========
// Block: 128 threads (4 warps), q-tile 128 rows, each warp owns m32 (2 m16 tiles).
// KV tiles of 64. Q fragments hoisted to registers; Q smem then reused for P.
#define QST 68   // Qs/Ps/Ks row stride (words)
#define VST 72   // Vs row stride (words): bank = 8t4+g distinct for V B-frags

__global__ __launch_bounds__(128)
void attn_tf32(const float* __restrict__ Q,
               const float* __restrict__ K,
               const float* __restrict__ V,
               float* __restrict__ out)
{
    extern __shared__ uint32_t sm[];
    uint32_t* QP = sm;                    // 128 x QST  (Q staging, then P)
    uint32_t* Ks = sm + 128 * QST;        // 64 x QST
    uint32_t* Vs = Ks + 64 * QST;         // 64 x VST

    const int tid  = threadIdx.x;
    const int wid  = tid >> 5;
    const int lane = tid & 31;
    const int g    = lane >> 2;
    const int t4   = lane & 3;
    const int m0   = wid * 32;

    const int qt = blockIdx.x;   // 0..15
    const int h  = blockIdx.y;
    const int bz = blockIdx.z;

    const size_t base = ((size_t)(bz * NHEADS + h)) * SEQ * HDIM;
    const float* Qg = Q + base + (size_t)qt * 128 * HDIM;

    // ---- stage Q tile -> smem (tf32) ----
    #pragma unroll
    for (int it = 0; it < 16; ++it) {
        const int lin = tid + it * 128;
        const int row = lin >> 4, d4 = (lin & 15) * 4;
        float4 v = *(const float4*)(Qg + row * HDIM + d4);
        uint4 u = {f2t(v.x), f2t(v.y), f2t(v.z), f2t(v.w)};
        *(uint4*)&QP[row * QST + d4] = u;
    }
    __syncthreads();

    // ---- hoist Q fragments to registers ----
    uint32_t qa[2][8][4];
    #pragma unroll
    for (int i = 0; i < 2; i++) {
        const int ra = m0 + i * 16 + g;
        #pragma unroll
        for (int k8 = 0; k8 < 8; k8++) {
            const int kb = k8 * 8;
            qa[i][k8][0] = QP[ra * QST + kb + t4];
            qa[i][k8][1] = QP[(ra + 8) * QST + kb + t4];
            qa[i][k8][2] = QP[ra * QST + kb + t4 + 4];
            qa[i][k8][3] = QP[(ra + 8) * QST + kb + t4 + 4];
        }
    }
    __syncthreads();   // QP free -> becomes P buffer

    float om[2][2], ol[2][2];
    float oacc[2][8][4];
    #pragma unroll
    for (int i = 0; i < 2; i++)
        #pragma unroll
        for (int hf = 0; hf < 2; hf++) { om[i][hf] = -1e30f; ol[i][hf] = 0.f; }
    #pragma unroll
    for (int i = 0; i < 2; i++)
        #pragma unroll
        for (int j = 0; j < 8; j++)
            #pragma unroll
            for (int r = 0; r < 4; r++) oacc[i][j][r] = 0.f;

    for (int kt = 0; kt < SEQ / 64; kt++) {
        __syncthreads();   // prior PV reads of Ks/Vs done
        const float* Kg = K + base + (size_t)kt * 64 * HDIM;
        const float* Vg = V + base + (size_t)kt * 64 * HDIM;
        #pragma unroll
        for (int it = 0; it < 8; ++it) {
            const int lin = tid + it * 128;
            const int row = lin >> 4, d4 = (lin & 15) * 4;
            float4 kv = *(const float4*)(Kg + row * HDIM + d4);
            uint4 uk = {f2t(kv.x), f2t(kv.y), f2t(kv.z), f2t(kv.w)};
            *(uint4*)&Ks[row * QST + d4] = uk;
            float4 vv = *(const float4*)(Vg + row * HDIM + d4);
            uint4 uv = {f2t(vv.x), f2t(vv.y), f2t(vv.z), f2t(vv.w)};
            *(uint4*)&Vs[row * VST + d4] = uv;
        }
        __syncthreads();

        // ---- scores S = Q K^T ----
        float s[2][8][4];
        #pragma unroll
        for (int i = 0; i < 2; i++)
            #pragma unroll
            for (int j = 0; j < 8; j++)
                #pragma unroll
                for (int r = 0; r < 4; r++) s[i][j][r] = 0.f;

        #pragma unroll
        for (int k8 = 0; k8 < 8; k8++) {
            const int kb = k8 * 8;
            uint32_t bf[8][2];
            #pragma unroll
            for (int j = 0; j < 8; j++) {
                bf[j][0] = Ks[(j * 8 + g) * QST + kb + t4];
                bf[j][1] = Ks[(j * 8 + g) * QST + kb + t4 + 4];
            }
            #pragma unroll
            for (int i = 0; i < 2; i++)
                #pragma unroll
                for (int j = 0; j < 8; j++)
                    mma_tf32(s[i][j], qa[i][k8], bf[j]);
        }

        // ---- online softmax (per row-half; row shared by 4 lanes of a quad) ----
        #pragma unroll
        for (int i = 0; i < 2; i++) {
            #pragma unroll
            for (int hf = 0; hf < 2; hf++) {
                float mx = -1e30f;
                #pragma unroll
                for (int j = 0; j < 8; j++) {
                    s[i][j][2 * hf]     *= 0.125f;
                    s[i][j][2 * hf + 1] *= 0.125f;
                    mx = fmaxf(mx, fmaxf(s[i][j][2 * hf], s[i][j][2 * hf + 1]));
                }
                mx = fmaxf(mx, __shfl_xor_sync(0xffffffffu, mx, 1));
                mx = fmaxf(mx, __shfl_xor_sync(0xffffffffu, mx, 2));
                const float mnew = fmaxf(om[i][hf], mx);
                const float alpha = __expf(om[i][hf] - mnew);
                om[i][hf] = mnew;
                float sum = 0.f;
                #pragma unroll
                for (int j = 0; j < 8; j++) {
                    float e0 = __expf(s[i][j][2 * hf] - mnew);
                    float e1 = __expf(s[i][j][2 * hf + 1] - mnew);
                    s[i][j][2 * hf] = e0; s[i][j][2 * hf + 1] = e1;
                    sum += e0 + e1;
                }
                sum += __shfl_xor_sync(0xffffffffu, sum, 1);
                sum += __shfl_xor_sync(0xffffffffu, sum, 2);
                ol[i][hf] = ol[i][hf] * alpha + sum;
                #pragma unroll
                for (int j = 0; j < 8; j++) {
                    oacc[i][j][2 * hf]     *= alpha;
                    oacc[i][j][2 * hf + 1] *= alpha;
                }
            }
        }

        // ---- store P (own warp's rows only) ----
        #pragma unroll
        for (int i = 0; i < 2; i++) {
            const int ra = m0 + i * 16 + g;
            #pragma unroll
            for (int j = 0; j < 8; j++) {
                const int col = j * 8 + 2 * t4;
                uint2 p0 = {f2t(s[i][j][0]), f2t(s[i][j][1])};
                uint2 p1 = {f2t(s[i][j][2]), f2t(s[i][j][3])};
                *(uint2*)&QP[ra * QST + col]       = p0;
                *(uint2*)&QP[(ra + 8) * QST + col] = p1;
            }
        }
        __syncwarp();

        // ---- O += P @ V ----
        #pragma unroll
        for (int k8 = 0; k8 < 8; k8++) {
            const int kb = k8 * 8;
            uint32_t pa[2][4], vb[8][2];
            #pragma unroll
            for (int i = 0; i < 2; i++) {
                const int ra = m0 + i * 16 + g;
                pa[i][0] = QP[ra * QST + kb + t4];
                pa[i][1] = QP[(ra + 8) * QST + kb + t4];
                pa[i][2] = QP[ra * QST + kb + t4 + 4];
                pa[i][3] = QP[(ra + 8) * QST + kb + t4 + 4];
            }
            #pragma unroll
            for (int j = 0; j < 8; j++) {
                vb[j][0] = Vs[(kb + t4) * VST + j * 8 + g];
                vb[j][1] = Vs[(kb + t4 + 4) * VST + j * 8 + g];
            }
            #pragma unroll
            for (int i = 0; i < 2; i++)
                #pragma unroll
                for (int j = 0; j < 8; j++)
                    mma_tf32(oacc[i][j], pa[i], vb[j]);
        }
    }

    // ---- epilogue: O / l -> merged layout [b][s][h*64+d] ----
    #pragma unroll
    for (int i = 0; i < 2; i++) {
        #pragma unroll
        for (int hf = 0; hf < 2; hf++) {
            const float inv = 1.f / ol[i][hf];
            const int row = qt * 128 + m0 + i * 16 + g + hf * 8;
            float* og = out + ((size_t)bz * SEQ + row) * DMODEL + h * HDIM;
            #pragma unroll
            for (int j = 0; j < 8; j++) {
                const int c = j * 8 + 2 * t4;
                float2 v = {oacc[i][j][2 * hf] * inv, oacc[i][j][2 * hf + 1] * inv};
                *(float2*)&og[c] = v;
            }
        }
    }
}

// ============================== launch ==============================
extern "C" void kernel_launch(void* const* d_in, const int* in_sizes, int n_in,
                              void* d_out, int out_size)
{
    const float* X  = (const float*)d_in[0];
    const float* Wq = (const float*)d_in[1];
    const float* bq = (const float*)d_in[2];
    const float* Wk = (const float*)d_in[3];
    const float* bk = (const float*)d_in[4];
    const float* Wv = (const float*)d_in[5];
    const float* bv = (const float*)d_in[6];
    const float* Wo = (const float*)d_in[7];
    const float* bo = (const float*)d_in[8];

    float *qp, *kp, *vp, *ap;
    cudaGetSymbolAddress((void**)&qp, g_q);
    cudaGetSymbolAddress((void**)&kp, g_k);
    cudaGetSymbolAddress((void**)&vp, g_v);
    cudaGetSymbolAddress((void**)&ap, g_att);

    dim3 ggrid(DMODEL / 128, MROWS / 128);   // (8, 32)
    gemm_tf32<true><<<ggrid, 256>>>(X, Wq, bq, qp);
    gemm_tf32<true><<<ggrid, 256>>>(X, Wk, bk, kp);
    gemm_tf32<true><<<ggrid, 256>>>(X, Wv, bv, vp);

    const size_t smem = (size_t)(128 * QST + 64 * QST + 64 * VST) * sizeof(uint32_t); // 70656 B
    cudaFuncSetAttribute(attn_tf32, cudaFuncAttributeMaxDynamicSharedMemorySize, (int)smem);
    attn_tf32<<<dim3(SEQ / 128, NHEADS, BATCH), 128, smem>>>(qp, kp, vp, ap);

    gemm_tf32<false><<<ggrid, 256>>>(ap, Wo, bo, (float*)d_out);
}

// round 3
// speedup vs baseline: 6.0626x; 1.0005x over previous
#include <cuda_runtime.h>
#include <cstdint>

#define BATCH   2
#define SEQ     2048
#define DMODEL  1024
#define NHEADS  16
#define HDIM    64
#define MROWS   (BATCH*SEQ)   // 4096

// -------- scratch (device globals; no allocation allowed) --------
__device__ float g_q[BATCH*NHEADS*SEQ*HDIM];   // [b][h][s][d]
__device__ float g_k[BATCH*NHEADS*SEQ*HDIM];
__device__ float g_v[BATCH*NHEADS*SEQ*HDIM];
__device__ float g_att[MROWS*DMODEL];          // merged [b][s][h*64+d]

// ---------------- tf32 helpers ----------------
__device__ __forceinline__ uint32_t f2t(float x) {
    uint32_t r;
    asm("cvt.rna.tf32.f32 %0, %1;" : "=r"(r) : "f"(x));
    return r;
}

// D += A * B   (m16n8k8, A row-major, B col-major, fp32 accum)
__device__ __forceinline__ void mma_tf32(float* d, const uint32_t* a, const uint32_t* b) {
    asm volatile(
        "mma.sync.aligned.m16n8k8.row.col.f32.tf32.tf32.f32 "
        "{%0,%1,%2,%3}, {%4,%5,%6,%7}, {%8,%9}, {%0,%1,%2,%3};\n"
        : "+f"(d[0]), "+f"(d[1]), "+f"(d[2]), "+f"(d[3])
        : "r"(a[0]), "r"(a[1]), "r"(a[2]), "r"(a[3]),
          "r"(b[0]), "r"(b[1]));
}

// ================= GEMM (tf32 tensor core) core ==========
// M=4096, N=K=1024. Block 128x128, BK=16, 256 threads = 8 warps (2x4), warp 64x32.
#define ASTRIDE 20     // As[m][k] row stride (words): bank = (20g + t4) distinct
#define BSTRIDE 136    // Bs[k][n] row stride (words): bank = (8t4 + g) distinct

template<bool HEADOUT>
__device__ __forceinline__
void gemm_body(const float* __restrict__ X,
               const float* __restrict__ W,
               const float* __restrict__ bias,
               float* __restrict__ out,
               int bx, int by)
{
    __shared__ uint32_t As[128 * ASTRIDE];
    __shared__ uint32_t Bs[16 * BSTRIDE];

    const int tid  = threadIdx.x;
    const int wid  = tid >> 5;
    const int lane = tid & 31;
    const int g    = lane >> 2;
    const int t4   = lane & 3;
    const int m0   = (wid & 1) * 64;
    const int n0   = (wid >> 1) * 32;

    const int am = tid >> 1;
    const int ak = (tid & 1) * 8;
    const int bk = tid >> 4;
    const int bn = (tid & 15) * 4;

    const float* Xp = X + (size_t)(by * 128 + am) * DMODEL;
    const float* Wp = W + bx * 128;

    float acc[4][4][4];
    #pragma unroll
    for (int i = 0; i < 4; i++)
        #pragma unroll
        for (int j = 0; j < 4; j++)
            #pragma unroll
            for (int r = 0; r < 4; r++) acc[i][j][r] = 0.f;

    float4 pa0 = *(const float4*)(Xp + ak);
    float4 pa1 = *(const float4*)(Xp + ak + 4);
    float4 pb0 = *(const float4*)(Wp + (size_t)bk * DMODEL + bn);
    float4 pb1 = *(const float4*)(Wp + (size_t)bk * DMODEL + bn + 64);

    for (int k0 = 0; k0 < DMODEL; k0 += 16) {
        {
            uint4 u0 = {f2t(pa0.x), f2t(pa0.y), f2t(pa0.z), f2t(pa0.w)};
            uint4 u1 = {f2t(pa1.x), f2t(pa1.y), f2t(pa1.z), f2t(pa1.w)};
            *(uint4*)&As[am * ASTRIDE + ak]     = u0;
            *(uint4*)&As[am * ASTRIDE + ak + 4] = u1;
            uint4 v0 = {f2t(pb0.x), f2t(pb0.y), f2t(pb0.z), f2t(pb0.w)};
            uint4 v1 = {f2t(pb1.x), f2t(pb1.y), f2t(pb1.z), f2t(pb1.w)};
            *(uint4*)&Bs[bk * BSTRIDE + bn]      = v0;
            *(uint4*)&Bs[bk * BSTRIDE + bn + 64] = v1;
        }
        __syncthreads();

        if (k0 + 16 < DMODEL) {
            pa0 = *(const float4*)(Xp + k0 + 16 + ak);
            pa1 = *(const float4*)(Xp + k0 + 16 + ak + 4);
            pb0 = *(const float4*)(Wp + (size_t)(k0 + 16 + bk) * DMODEL + bn);
            pb1 = *(const float4*)(Wp + (size_t)(k0 + 16 + bk) * DMODEL + bn + 64);
        }

        #pragma unroll
        for (int kk = 0; kk < 16; kk += 8) {
            uint32_t af[4][4], bf[4][2];
            #pragma unroll
            for (int j = 0; j < 4; j++) {
                bf[j][0] = Bs[(kk + t4) * BSTRIDE + n0 + j * 8 + g];
                bf[j][1] = Bs[(kk + t4 + 4) * BSTRIDE + n0 + j * 8 + g];
            }
            #pragma unroll
            for (int i = 0; i < 4; i++) {
                const int ra = m0 + i * 16 + g;
                af[i][0] = As[ra * ASTRIDE + kk + t4];
                af[i][1] = As[(ra + 8) * ASTRIDE + kk + t4];
                af[i][2] = As[ra * ASTRIDE + kk + t4 + 4];
                af[i][3] = As[(ra + 8) * ASTRIDE + kk + t4 + 4];
            }
            #pragma unroll
            for (int i = 0; i < 4; i++)
                #pragma unroll
                for (int j = 0; j < 4; j++)
                    mma_tf32(acc[i][j], af[i], bf[j]);
        }
        __syncthreads();
    }

    #pragma unroll
    for (int i = 0; i < 4; i++) {
        const int Ra = by * 128 + m0 + i * 16 + g;
        #pragma unroll
        for (int j = 0; j < 4; j++) {
            const int c = bx * 128 + n0 + j * 8 + 2 * t4;
            const float b0v = bias[c], b1v = bias[c + 1];
            float2 v0 = {acc[i][j][0] + b0v, acc[i][j][1] + b1v};
            float2 v1 = {acc[i][j][2] + b0v, acc[i][j][3] + b1v};
            if (HEADOUT) {
                const int h = c >> 6, d = c & 63;
                {
                    const int bb = Ra >> 11, s = Ra & 2047;
                    *(float2*)&out[(((size_t)(bb * NHEADS + h) * SEQ) + s) * HDIM + d] = v0;
                }
                {
                    const int R2 = Ra + 8;
                    const int bb = R2 >> 11, s = R2 & 2047;
                    *(float2*)&out[(((size_t)(bb * NHEADS + h) * SEQ) + s) * HDIM + d] = v1;
                }
            } else {
                *(float2*)&out[(size_t)Ra * DMODEL + c] = v0;
                *(float2*)&out[(size_t)(Ra + 8) * DMODEL + c] = v1;
            }
        }
    }
}

// fused QKV projection: z selects Wq/Wk/Wv
__global__ __launch_bounds__(256, 2)
void gemm_qkv(const float* __restrict__ X,
              const float* __restrict__ Wq, const float* __restrict__ bq, float* __restrict__ q,
              const float* __restrict__ Wk, const float* __restrict__ bk, float* __restrict__ k,
              const float* __restrict__ Wv, const float* __restrict__ bv, float* __restrict__ v)
{
    const int z = blockIdx.z;
    const float* W  = (z == 0) ? Wq : (z == 1) ? Wk : Wv;
    const float* bb = (z == 0) ? bq : (z == 1) ? bk : bv;
    float*       o  = (z == 0) ? q  : (z == 1) ? k  : v;
    gemm_body<true>(X, W, bb, o, blockIdx.x, blockIdx.y);
}

__global__ __launch_bounds__(256, 2)
void gemm_out(const float* __restrict__ X,
              const float* __restrict__ W,
              const float* __restrict__ bias,
              float* __restrict__ out)
{
    gemm_body<false>(X, W, bias, out, blockIdx.x, blockIdx.y);
}

// ========== Flash attention, tf32 tensor cores ==========
// Block: 256 threads (8 warps), q-tile 128 rows, each warp owns m16.
// KV tiles of 64. Q fragments hoisted to registers; Q smem then reused for P.
#define QST 68   // Qs/Ps/Ks row stride (words)
#define VST 72   // Vs row stride (words)

__global__ __launch_bounds__(256, 2)
void attn_tf32(const float* __restrict__ Q,
               const float* __restrict__ K,
               const float* __restrict__ V,
               float* __restrict__ out)
{
    extern __shared__ uint32_t sm[];
    uint32_t* QP = sm;                    // 128 x QST  (Q staging, then P)
    uint32_t* Ks = sm + 128 * QST;        // 64 x QST
    uint32_t* Vs = Ks + 64 * QST;         // 64 x VST

    const int tid  = threadIdx.x;
    const int wid  = tid >> 5;     // 0..7
    const int lane = tid & 31;
    const int g    = lane >> 2;
    const int t4   = lane & 3;
    const int m0   = wid * 16;

    const int qt = blockIdx.x;   // 0..15
    const int h  = blockIdx.y;
    const int bz = blockIdx.z;

    const size_t base = ((size_t)(bz * NHEADS + h)) * SEQ * HDIM;
    const float* Qg = Q + base + (size_t)qt * 128 * HDIM;

    // ---- stage Q tile -> smem (tf32): 128x64 = 2048 float4, 256 thr, 8 it ----
    #pragma unroll
    for (int it = 0; it < 8; ++it) {
        const int lin = tid + it * 256;
        const int row = lin >> 4, d4 = (lin & 15) * 4;
        float4 v = *(const float4*)(Qg + row * HDIM + d4);
        uint4 u = {f2t(v.x), f2t(v.y), f2t(v.z), f2t(v.w)};
        *(uint4*)&QP[row * QST + d4] = u;
    }
    __syncthreads();

    // ---- hoist Q fragments (own warp's m16 rows only) ----
    uint32_t qa[8][4];
    {
        const int ra = m0 + g;
        #pragma unroll
        for (int k8 = 0; k8 < 8; k8++) {
            const int kb = k8 * 8;
            qa[k8][0] = QP[ra * QST + kb + t4];
            qa[k8][1] = QP[(ra + 8) * QST + kb + t4];
            qa[k8][2] = QP[ra * QST + kb + t4 + 4];
            qa[k8][3] = QP[(ra + 8) * QST + kb + t4 + 4];
        }
    }
    // No cross-warp hazard: each warp reads/writes only its own 16 QP rows.

    float om[2] = {-1e30f, -1e30f}, ol[2] = {0.f, 0.f};
    float oacc[8][4];
    #pragma unroll
    for (int j = 0; j < 8; j++)
        #pragma unroll
        for (int r = 0; r < 4; r++) oacc[j][r] = 0.f;

    for (int kt = 0; kt < SEQ / 64; kt++) {
        __syncthreads();   // prior iter's Ks/Vs reads done
        const float* Kg = K + base + (size_t)kt * 64 * HDIM;
        const float* Vg = V + base + (size_t)kt * 64 * HDIM;
        #pragma unroll
        for (int it = 0; it < 4; ++it) {
            const int lin = tid + it * 256;
            const int row = lin >> 4, d4 = (lin & 15) * 4;
            float4 kv = *(const float4*)(Kg + row * HDIM + d4);
            uint4 uk = {f2t(kv.x), f2t(kv.y), f2t(kv.z), f2t(kv.w)};
            *(uint4*)&Ks[row * QST + d4] = uk;
            float4 vv = *(const float4*)(Vg + row * HDIM + d4);
            uint4 uv = {f2t(vv.x), f2t(vv.y), f2t(vv.z), f2t(vv.w)};
            *(uint4*)&Vs[row * VST + d4] = uv;
        }
        __syncthreads();

        // ---- scores S = Q K^T ----
        float s[8][4];
        #pragma unroll
        for (int j = 0; j < 8; j++)
            #pragma unroll
            for (int r = 0; r < 4; r++) s[j][r] = 0.f;

        #pragma unroll
        for (int k8 = 0; k8 < 8; k8++) {
            const int kb = k8 * 8;
            uint32_t bf[8][2];
            #pragma unroll
            for (int j = 0; j < 8; j++) {
                bf[j][0] = Ks[(j * 8 + g) * QST + kb + t4];
                bf[j][1] = Ks[(j * 8 + g) * QST + kb + t4 + 4];
            }
            #pragma unroll
            for (int j = 0; j < 8; j++)
                mma_tf32(s[j], qa[k8], bf[j]);
        }

        // ---- online softmax (hf=0: row g; hf=1: row g+8) ----
        #pragma unroll
        for (int hf = 0; hf < 2; hf++) {
            float mx = -1e30f;
            #pragma unroll
            for (int j = 0; j < 8; j++) {
                s[j][2 * hf]     *= 0.125f;
                s[j][2 * hf + 1] *= 0.125f;
                mx = fmaxf(mx, fmaxf(s[j][2 * hf], s[j][2 * hf + 1]));
            }
            mx = fmaxf(mx, __shfl_xor_sync(0xffffffffu, mx, 1));
            mx = fmaxf(mx, __shfl_xor_sync(0xffffffffu, mx, 2));
            const float mnew = fmaxf(om[hf], mx);
            const float alpha = __expf(om[hf] - mnew);
            om[hf] = mnew;
            float sum = 0.f;
            #pragma unroll
            for (int j = 0; j < 8; j++) {
                float e0 = __expf(s[j][2 * hf] - mnew);
                float e1 = __expf(s[j][2 * hf + 1] - mnew);
                s[j][2 * hf] = e0; s[j][2 * hf + 1] = e1;
                sum += e0 + e1;
            }
            sum += __shfl_xor_sync(0xffffffffu, sum, 1);
            sum += __shfl_xor_sync(0xffffffffu, sum, 2);
            ol[hf] = ol[hf] * alpha + sum;
            #pragma unroll
            for (int j = 0; j < 8; j++) {
                oacc[j][2 * hf]     *= alpha;
                oacc[j][2 * hf + 1] *= alpha;
            }
        }

        // ---- store P (own warp's 16 rows) ----
        {
            const int ra = m0 + g;
            #pragma unroll
            for (int j = 0; j < 8; j++) {
                const int col = j * 8 + 2 * t4;
                uint2 p0 = {f2t(s[j][0]), f2t(s[j][1])};
                uint2 p1 = {f2t(s[j][2]), f2t(s[j][3])};
                *(uint2*)&QP[ra * QST + col]       = p0;
                *(uint2*)&QP[(ra + 8) * QST + col] = p1;
            }
        }
        __syncwarp();

        // ---- O += P @ V ----
        #pragma unroll
        for (int k8 = 0; k8 < 8; k8++) {
            const int kb = k8 * 8;
            uint32_t pa[4], vb[8][2];
            {
                const int ra = m0 + g;
                pa[0] = QP[ra * QST + kb + t4];
                pa[1] = QP[(ra + 8) * QST + kb + t4];
                pa[2] = QP[ra * QST + kb + t4 + 4];
                pa[3] = QP[(ra + 8) * QST + kb + t4 + 4];
            }
            #pragma unroll
            for (int j = 0; j < 8; j++) {
                vb[j][0] = Vs[(kb + t4) * VST + j * 8 + g];
                vb[j][1] = Vs[(kb + t4 + 4) * VST + j * 8 + g];
            }
            #pragma unroll
            for (int j = 0; j < 8; j++)
                mma_tf32(oacc[j], pa, vb[j]);
        }
    }

    // ---- epilogue: O / l -> merged layout [b][s][h*64+d] ----
    #pragma unroll
    for (int hf = 0; hf < 2; hf++) {
        const float inv = 1.f / ol[hf];
        const int row = qt * 128 + m0 + g + hf * 8;
        float* og = out + ((size_t)bz * SEQ + row) * DMODEL + h * HDIM;
        #pragma unroll
        for (int j = 0; j < 8; j++) {
            const int c = j * 8 + 2 * t4;
            float2 v = {oacc[j][2 * hf] * inv, oacc[j][2 * hf + 1] * inv};
            *(float2*)&og[c] = v;
        }
    }
}

// ============================== launch ==============================
extern "C" void kernel_launch(void* const* d_in, const int* in_sizes, int n_in,
                              void* d_out, int out_size)
{
    const float* X  = (const float*)d_in[0];
    const float* Wq = (const float*)d_in[1];
    const float* bq = (const float*)d_in[2];
    const float* Wk = (const float*)d_in[3];
    const float* bk = (const float*)d_in[4];
    const float* Wv = (const float*)d_in[5];
    const float* bv = (const float*)d_in[6];
    const float* Wo = (const float*)d_in[7];
    const float* bo = (const float*)d_in[8];

    float *qp, *kp, *vp, *ap;
    cudaGetSymbolAddress((void**)&qp, g_q);
    cudaGetSymbolAddress((void**)&kp, g_k);
    cudaGetSymbolAddress((void**)&vp, g_v);
    cudaGetSymbolAddress((void**)&ap, g_att);

    dim3 qkvgrid(DMODEL / 128, MROWS / 128, 3);   // (8, 32, 3)
    gemm_qkv<<<qkvgrid, 256>>>(X, Wq, bq, qp, Wk, bk, kp, Wv, bv, vp);

    const size_t smem = (size_t)(128 * QST + 64 * QST + 64 * VST) * sizeof(uint32_t); // 70656 B
    cudaFuncSetAttribute(attn_tf32, cudaFuncAttributeMaxDynamicSharedMemorySize, (int)smem);
    attn_tf32<<<dim3(SEQ / 128, NHEADS, BATCH), 256, smem>>>(qp, kp, vp, ap);

    gemm_out<<<dim3(DMODEL / 128, MROWS / 128), 256>>>(ap, Wo, bo, (float*)d_out);
}